// round 16
// baseline (speedup 1.0000x reference)
#include <cuda_runtime.h>
#include <cuda_fp16.h>

#define I_DIM   128
#define O_DIM   128
#define G_NUM   128
#define G1      129
#define B_DIM   8192
#define C_CHUNKS 4
#define ICHUNK  (I_DIM / C_CHUNKS)   /* 32 */
#define BT      256                  /* batch columns per block */
#define NBT     (B_DIM / BT)         /* 32 */
#define THREADS 512
#define NWARP   (THREADS / 32)       /* 16 */
#define BPW     (BT / NWARP)         /* 16 batch columns per warp */
#define TI      16                   /* i per transpose tile */
#define JSPLIT  5                    /* jj<5 -> smem pipe, jj>=5 -> L1 pipe */

#define SLB2    (G1 * 256)           /* 33024 B: one full fp16 slice */
#define SLB_U4  (SLB2 / 16)          /* 2064 cp.async units */

// dynamic smem layout (main kernel)
#define OFF_RING  0                          /* 4 x 33024 = 132096 */
#define OFF_GD    (4 * SLB2)                 /* 32768 descriptors */
#define OFF_SB    (OFF_GD + ICHUNK * BT * 4) /* 164864 */
#define OFF_SIL   (OFF_SB + 132 * 4)         /* 165392 */
#define SMEM_MAIN (OFF_SIL + 128 * 4 + 32)   /* 165936 < 227KB */

// Static device scratch (allocation-free per harness rules)
__device__ __align__(256) __half g_P2h[(size_t)I_DIM * G1 * O_DIM];   // [i][g][o]
__device__ __align__(16) __half g_partialH[C_CHUNKS][B_DIM][O_DIM];   // [c][b][o]

// ---------------------------------------------------------------------------
__device__ __forceinline__ void cp16(unsigned dst_smem, const void* src) {
    asm volatile("cp.async.cg.shared.global [%0], [%1], 16;"
                 :: "r"(dst_smem), "l"(src) : "memory");
}
__device__ __forceinline__ void cp_commit() {
    asm volatile("cp.async.commit_group;" ::: "memory");
}
template <int N>
__device__ __forceinline__ void cp_wait() {
    asm volatile("cp.async.wait_group %0;" :: "n"(N) : "memory");
}

// ---------------------------------------------------------------------------
// Kernel 1 (stable): transpose+quantize P[g][o][i] -> P2h[i][g][o].
// ---------------------------------------------------------------------------
__global__ __launch_bounds__(256, 8)
void transpose_kernel(const float* __restrict__ P) {
    __shared__ float tile[2][O_DIM][17];
    const int g0 = blockIdx.y * 2;
    const int i0 = blockIdx.x * TI;
    const int t = threadIdx.x;
    const int w = t >> 5, lane = t & 31;
    const int gg = w >> 2;
    const int w2 = w & 3;
    const int oq = lane >> 2;
    const int f4 = lane & 3;
    const int g = g0 + gg;

    if (g <= G_NUM) {
        const float4* src = (const float4*)(P + (size_t)g * O_DIM * I_DIM + i0);
        float4 v[4];
#pragma unroll
        for (int r = 0; r < 4; r++) {
            int o = w2 * 32 + r * 8 + oq;
            v[r] = src[(size_t)o * (I_DIM / 4) + f4];
        }
#pragma unroll
        for (int r = 0; r < 4; r++) {
            int o = w2 * 32 + r * 8 + oq;
            tile[gg][o][f4 * 4 + 0] = v[r].x;
            tile[gg][o][f4 * 4 + 1] = v[r].y;
            tile[gg][o][f4 * 4 + 2] = v[r].z;
            tile[gg][o][f4 * 4 + 3] = v[r].w;
        }
    }
    __syncthreads();

    const int op  = t & 63;
    const int il  = (t >> 6) & 1;
    const int gg2 = t >> 7;
    const int gs  = g0 + gg2;
    if (gs <= G_NUM) {
        __half2* dst = (__half2*)g_P2h;
#pragma unroll
        for (int r = 0; r < 8; r++) {
            int i = il + 2 * r;
            dst[((size_t)(i0 + i) * G1 + gs) * (O_DIM / 2) + op] =
                __floats2half2_rn(tile[gg2][2 * op][i], tile[gg2][2 * op + 1][i]);
        }
    }
}

// ---------------------------------------------------------------------------
// Kernel 2: DUAL-PIPE gather on the proven round-15 skeleton. Slices are
// staged into a 4-deep smem ring via cp.async.cg (bypasses L1). Per warp,
// col-pairs jj<JSPLIT gather from smem (LDS.128, conflict-free crossbar);
// jj>=JSPLIT gather straight from the L2-resident global table via __ldg
// (L1 pipe, otherwise idle). Compile-time split, zero divergence.
// ---------------------------------------------------------------------------
__global__ __launch_bounds__(THREADS, 1)
void main_kernel(const float* __restrict__ x,
                 const float* __restrict__ borders,
                 const float* __restrict__ invl) {
    extern __shared__ __align__(16) char dyn[];
    unsigned* s_gd = (unsigned*)(dyn + OFF_GD);   // [ICHUNK][BT]
    float*    s_b  = (float*)(dyn + OFF_SB);
    float*    s_il = (float*)(dyn + OFF_SIL);
    const unsigned ringS = (unsigned)__cvta_generic_to_shared(dyn + OFF_RING);

    const int t     = threadIdx.x;
    const int btile = blockIdx.x;    // 0..31
    const int chunk = blockIdx.y;    // 0..3
    const int b0    = btile * BT;
    const int i0    = chunk * ICHUNK;

    if (t < G1)    s_b[t]  = borders[t];
    if (t < G_NUM) s_il[t] = invl[t];

    // Prologue: stage slices i0..i0+2 into ring bufs 0..2 (flies over phase 1)
    const char* gbase = (const char*)g_P2h + (size_t)i0 * SLB2;
#pragma unroll
    for (int s = 0; s < 3; s++) {
        for (int k = t; k < SLB_U4; k += THREADS)
            cp16(ringS + s * SLB2 + k * 16, gbase + (size_t)s * SLB2 + k * 16);
        cp_commit();
    }
    __syncthreads();   // s_b/s_il visible

    // Phase 1: bucket index g + weight d, packed (g | half(d)<<16)
    {
        const int bl    = t & (BT - 1);
        const int ibase = t >> 8;
#pragma unroll
        for (int p = 0; p < ICHUNK / 2; p++) {
            int il = ibase + 2 * p;
            float xv = x[(size_t)(i0 + il) * B_DIM + b0 + bl];
            float e  = __expf(-fabsf(xv));
            float cdf = (xv > 0.f) ? (1.f - 0.5f * e) : (0.5f * e);
            int g = (int)(cdf * (float)G_NUM);
            g = min(max(g, 0), G_NUM - 1);
            float d = (xv - s_b[g]) * s_il[g];
            unsigned db = (unsigned)__half_as_ushort(__float2half_rn(d));
            s_gd[il * BT + bl] = (unsigned)g | (db << 16);
        }
    }
    __syncthreads();

    const int w    = t >> 5;
    const int lane = t & 31;
    const int wb   = w * BPW;        // 16 cols per warp
    const int h    = lane >> 4;      // 0..1: column within pair
    const int le   = lane & 15;      // 16B chunk (8 outputs) of 256B row

    const __half2 one2 = __floats2half2_rn(1.f, 1.f);
    const __half2 z2   = __floats2half2_rn(0.f, 0.f);

    float4 accF[8][2];               // 8 col-pairs x 8 outputs fp32
#pragma unroll
    for (int jj = 0; jj < 8; jj++) {
        accF[jj][0] = make_float4(0.f, 0.f, 0.f, 0.f);
        accF[jj][1] = make_float4(0.f, 0.f, 0.f, 0.f);
    }

    for (int W = 0; W < ICHUNK / 4; W++) {
        __half2 hac[8][4];
#pragma unroll
        for (int jj = 0; jj < 8; jj++) {
            hac[jj][0] = z2; hac[jj][1] = z2; hac[jj][2] = z2; hac[jj][3] = z2;
        }

#pragma unroll
        for (int u = 0; u < 4; u++) {
            const int ii = W * 4 + u;
            cp_wait<2>();      // slice ii resident in buf[ii&3]
            __syncthreads();   // all warps past slice ii-1 -> its buf is free

            if (ii + 3 < ICHUNK) {
                const char* src = gbase + (size_t)(ii + 3) * SLB2;
                unsigned dst = ringS + ((ii + 3) & 3) * SLB2;
                for (int k = t; k < SLB_U4; k += THREADS)
                    cp16(dst + k * 16, src + k * 16);
            }
            cp_commit();   // unconditional: uniform group bookkeeping

            const char* sbuf = dyn + OFF_RING + (ii & 3) * SLB2;
            const uint4* gsl = (const uint4*)((const char*)g_P2h +
                                              (size_t)(i0 + ii) * SLB2);
#pragma unroll
            for (int jj = 0; jj < 8; jj++) {
                unsigned v  = s_gd[ii * BT + wb + 2 * jj + h];  // 2-way bcast
                unsigned gi = v & 0xFFu;
                unsigned dd = __byte_perm(v, v, 0x3232);
                __half2 d2  = *(__half2*)&dd;
                __half2 w2  = __hsub2(one2, d2);
                uint4 A, Bv;
                if (jj < JSPLIT) {           // crossbar pipe (staged slice)
                    const uint4* pa = (const uint4*)(sbuf + gi * 256) + le;
                    A  = pa[0];              // row g   (LDS.128, conflict-free)
                    Bv = pa[16];             // row g+1 (+256B)
                } else {                     // L1 pipe (L2-resident table)
                    const uint4* pa = gsl + gi * 16 + le;
                    A  = __ldg(pa);          // row g
                    Bv = __ldg(pa + 16);     // row g+1
                }
                hac[jj][0] = __hfma2(d2, *(__half2*)&Bv.x, __hfma2(w2, *(__half2*)&A.x, hac[jj][0]));
                hac[jj][1] = __hfma2(d2, *(__half2*)&Bv.y, __hfma2(w2, *(__half2*)&A.y, hac[jj][1]));
                hac[jj][2] = __hfma2(d2, *(__half2*)&Bv.z, __hfma2(w2, *(__half2*)&A.z, hac[jj][2]));
                hac[jj][3] = __hfma2(d2, *(__half2*)&Bv.w, __hfma2(w2, *(__half2*)&A.w, hac[jj][3]));
            }
        }

        // flush half2 partials into fp32 accumulators every 4 slices
#pragma unroll
        for (int jj = 0; jj < 8; jj++) {
            float2 p0 = __half22float2(hac[jj][0]);
            float2 p1 = __half22float2(hac[jj][1]);
            float2 p2 = __half22float2(hac[jj][2]);
            float2 p3 = __half22float2(hac[jj][3]);
            accF[jj][0].x += p0.x; accF[jj][0].y += p0.y;
            accF[jj][0].z += p1.x; accF[jj][0].w += p1.y;
            accF[jj][1].x += p2.x; accF[jj][1].y += p2.y;
            accF[jj][1].z += p3.x; accF[jj][1].w += p3.y;
        }
    }

    // Store: lane's column = wb + 2jj + h, outputs [8le, 8le+8) -> uint4.
#pragma unroll
    for (int jj = 0; jj < 8; jj++) {
        __half2 q0 = __floats2half2_rn(accF[jj][0].x, accF[jj][0].y);
        __half2 q1 = __floats2half2_rn(accF[jj][0].z, accF[jj][0].w);
        __half2 q2 = __floats2half2_rn(accF[jj][1].x, accF[jj][1].y);
        __half2 q3 = __floats2half2_rn(accF[jj][1].z, accF[jj][1].w);
        uint4 pk;
        pk.x = *(unsigned*)&q0; pk.y = *(unsigned*)&q1;
        pk.z = *(unsigned*)&q2; pk.w = *(unsigned*)&q3;
        int b = b0 + wb + 2 * jj + h;
        *(uint4*)&g_partialH[chunk][b][le * 8] = pk;
    }
}

// ---------------------------------------------------------------------------
// Kernel 3 (stable): sum the 4 fp16 partials, transpose -> out[o][b].
// ---------------------------------------------------------------------------
__global__ void reduce_kernel(float* __restrict__ out) {
    __shared__ float4 tile[32][33];
    const int b0 = blockIdx.x * 32;
    const int tx = threadIdx.x, ty = threadIdx.y;   // (32, 8)
    const size_t cstride = (size_t)B_DIM * (O_DIM / 4);   // in uint2

    const uint2* pbase = (const uint2*)&g_partialH[0][0][0];
#pragma unroll
    for (int r = 0; r < 4; r++) {
        int b = ty + r * 8;
        const uint2* p = pbase + (size_t)(b0 + b) * (O_DIM / 4) + tx;
        float4 s = make_float4(0.f, 0.f, 0.f, 0.f);
#pragma unroll
        for (int c = 0; c < C_CHUNKS; c++) {
            uint2 v = p[c * cstride];
            float2 f0 = __half22float2(*(const __half2*)&v.x);
            float2 f1 = __half22float2(*(const __half2*)&v.y);
            s.x += f0.x; s.y += f0.y; s.z += f1.x; s.w += f1.y;
        }
        tile[b][tx] = s;
    }
    __syncthreads();

    const float* tf = (const float*)tile;   // row stride = 132 floats
#pragma unroll
    for (int r = 0; r < 16; r++) {
        int o = ty + r * 8;
        out[(size_t)o * B_DIM + b0 + tx] = tf[tx * 132 + o];
    }
}

// ---------------------------------------------------------------------------
extern "C" void kernel_launch(void* const* d_in, const int* in_sizes, int n_in,
                              void* d_out, int out_size) {
    const float* x       = (const float*)d_in[0];   // [128, 8192]
    const float* P       = (const float*)d_in[1];   // [129, 128, 128]
    const float* borders = (const float*)d_in[2];   // [129]
    const float* invl    = (const float*)d_in[3];   // [128]
    float*       out     = (float*)d_out;           // [128, 8192]

    cudaFuncSetAttribute(main_kernel,
                         cudaFuncAttributeMaxDynamicSharedMemorySize, SMEM_MAIN);

    transpose_kernel<<<dim3(I_DIM / TI, 65), 256>>>(P);
    main_kernel<<<dim3(NBT, C_CHUNKS), THREADS, SMEM_MAIN>>>(x, borders, invl);
    reduce_kernel<<<B_DIM / 32, dim3(32, 8)>>>(out);
}

// round 17
// speedup vs baseline: 1.0463x; 1.0463x over previous
#include <cuda_runtime.h>
#include <cuda_fp16.h>

#define I_DIM   128
#define O_DIM   128
#define G_NUM   128
#define G1      129
#define B_DIM   8192
#define C_CHUNKS 4
#define ICHUNK  (I_DIM / C_CHUNKS)   /* 32 */
#define BT      256                  /* batch columns per block */
#define NBT     (B_DIM / BT)         /* 32 */
#define THREADS 512
#define NWARP   (THREADS / 32)       /* 16 */
#define BPW     (BT / NWARP)         /* 16 batch columns per warp */
#define TI      16                   /* i per transpose tile */

#define SLB2    (G1 * 256)           /* 33024 B: one full fp16 slice */
#define SLB_U4  (SLB2 / 16)          /* 2064 cp.async units */

// dynamic smem layout (main kernel)
#define OFF_RING  0                          /* 4 x 33024 = 132096 */
#define OFF_GD    (4 * SLB2)                 /* 32768 descriptors */
#define OFF_SB    (OFF_GD + ICHUNK * BT * 4) /* 164864 */
#define OFF_SIL   (OFF_SB + 132 * 4)         /* 165392 */
#define SMEM_MAIN (OFF_SIL + 128 * 4 + 32)   /* 165936 < 227KB */

// Static device scratch (allocation-free per harness rules)
__device__ __align__(256) __half g_P2h[(size_t)I_DIM * G1 * O_DIM];   // [i][g][o]
__device__ __align__(16) __half g_partialH[C_CHUNKS][B_DIM][O_DIM];   // [c][b][o]

// ---------------------------------------------------------------------------
__device__ __forceinline__ void cp16(unsigned dst_smem, const void* src) {
    asm volatile("cp.async.cg.shared.global [%0], [%1], 16;"
                 :: "r"(dst_smem), "l"(src) : "memory");
}
__device__ __forceinline__ void cp_commit() {
    asm volatile("cp.async.commit_group;" ::: "memory");
}
template <int N>
__device__ __forceinline__ void cp_wait() {
    asm volatile("cp.async.wait_group %0;" :: "n"(N) : "memory");
}

// ---------------------------------------------------------------------------
// Kernel 1 (stable): transpose+quantize P[g][o][i] -> P2h[i][g][o].
// ---------------------------------------------------------------------------
__global__ __launch_bounds__(256, 8)
void transpose_kernel(const float* __restrict__ P) {
    __shared__ float tile[2][O_DIM][17];
    const int g0 = blockIdx.y * 2;
    const int i0 = blockIdx.x * TI;
    const int t = threadIdx.x;
    const int w = t >> 5, lane = t & 31;
    const int gg = w >> 2;
    const int w2 = w & 3;
    const int oq = lane >> 2;
    const int f4 = lane & 3;
    const int g = g0 + gg;

    if (g <= G_NUM) {
        const float4* src = (const float4*)(P + (size_t)g * O_DIM * I_DIM + i0);
        float4 v[4];
#pragma unroll
        for (int r = 0; r < 4; r++) {
            int o = w2 * 32 + r * 8 + oq;
            v[r] = src[(size_t)o * (I_DIM / 4) + f4];
        }
#pragma unroll
        for (int r = 0; r < 4; r++) {
            int o = w2 * 32 + r * 8 + oq;
            tile[gg][o][f4 * 4 + 0] = v[r].x;
            tile[gg][o][f4 * 4 + 1] = v[r].y;
            tile[gg][o][f4 * 4 + 2] = v[r].z;
            tile[gg][o][f4 * 4 + 3] = v[r].w;
        }
    }
    __syncthreads();

    const int op  = t & 63;
    const int il  = (t >> 6) & 1;
    const int gg2 = t >> 7;
    const int gs  = g0 + gg2;
    if (gs <= G_NUM) {
        __half2* dst = (__half2*)g_P2h;
#pragma unroll
        for (int r = 0; r < 8; r++) {
            int i = il + 2 * r;
            dst[((size_t)(i0 + i) * G1 + gs) * (O_DIM / 2) + op] =
                __floats2half2_rn(tile[gg2][2 * op][i], tile[gg2][2 * op + 1][i]);
        }
    }
}

// ---------------------------------------------------------------------------
// Kernel 2: per-SLICE dual-pipe gather. Slices with (ii&3)<3 are staged into
// the smem ring (cp.async.cg, bypasses L1) and gathered via conflict-free
// LDS.128 (crossbar pipe). Slices with (ii&3)==3 are NEVER staged: gathered
// straight from the L2-resident table via uint4 LDG (L1 pipe) in their own
// unrolled iteration -> no per-gather branch, no extra register pressure.
// ---------------------------------------------------------------------------
__global__ __launch_bounds__(THREADS, 1)
void main_kernel(const float* __restrict__ x,
                 const float* __restrict__ borders,
                 const float* __restrict__ invl) {
    extern __shared__ __align__(16) char dyn[];
    unsigned* s_gd = (unsigned*)(dyn + OFF_GD);   // [ICHUNK][BT]
    float*    s_b  = (float*)(dyn + OFF_SB);
    float*    s_il = (float*)(dyn + OFF_SIL);
    const unsigned ringS = (unsigned)__cvta_generic_to_shared(dyn + OFF_RING);

    const int t     = threadIdx.x;
    const int btile = blockIdx.x;    // 0..31
    const int chunk = blockIdx.y;    // 0..3
    const int b0    = btile * BT;
    const int i0    = chunk * ICHUNK;

    if (t < G1)    s_b[t]  = borders[t];
    if (t < G_NUM) s_il[t] = invl[t];

    // Prologue: stage slices i0..i0+2 into ring bufs 0..2 (flies over phase 1)
    const char* gbase = (const char*)g_P2h + (size_t)i0 * SLB2;
#pragma unroll
    for (int s = 0; s < 3; s++) {
        for (int k = t; k < SLB_U4; k += THREADS)
            cp16(ringS + s * SLB2 + k * 16, gbase + (size_t)s * SLB2 + k * 16);
        cp_commit();
    }
    __syncthreads();   // s_b/s_il visible

    // Phase 1: bucket index g + weight d, packed (g | half(d)<<16)
    {
        const int bl    = t & (BT - 1);
        const int ibase = t >> 8;
#pragma unroll
        for (int p = 0; p < ICHUNK / 2; p++) {
            int il = ibase + 2 * p;
            float xv = x[(size_t)(i0 + il) * B_DIM + b0 + bl];
            float e  = __expf(-fabsf(xv));
            float cdf = (xv > 0.f) ? (1.f - 0.5f * e) : (0.5f * e);
            int g = (int)(cdf * (float)G_NUM);
            g = min(max(g, 0), G_NUM - 1);
            float d = (xv - s_b[g]) * s_il[g];
            unsigned db = (unsigned)__half_as_ushort(__float2half_rn(d));
            s_gd[il * BT + bl] = (unsigned)g | (db << 16);
        }
    }
    __syncthreads();

    const int w    = t >> 5;
    const int lane = t & 31;
    const int wb   = w * BPW;        // 16 cols per warp
    const int h    = lane >> 4;      // 0..1: column within pair
    const int le   = lane & 15;      // 16B chunk (8 outputs) of 256B row

    const __half2 one2 = __floats2half2_rn(1.f, 1.f);
    const __half2 z2   = __floats2half2_rn(0.f, 0.f);

    float4 accF[8][2];               // 8 col-pairs x 8 outputs fp32
#pragma unroll
    for (int jj = 0; jj < 8; jj++) {
        accF[jj][0] = make_float4(0.f, 0.f, 0.f, 0.f);
        accF[jj][1] = make_float4(0.f, 0.f, 0.f, 0.f);
    }

    for (int W = 0; W < ICHUNK / 4; W++) {
        __half2 hac[8][4];
#pragma unroll
        for (int jj = 0; jj < 8; jj++) {
            hac[jj][0] = z2; hac[jj][1] = z2; hac[jj][2] = z2; hac[jj][3] = z2;
        }

#pragma unroll
        for (int u = 0; u < 4; u++) {
            const int ii = W * 4 + u;
            cp_wait<2>();      // staged slice ii resident (if staged)
            __syncthreads();   // all warps past slice ii-1 -> its buf is free

            // Refill slice ii+3 UNLESS it's an L1-routed slice ((ii+3)&3==3
            // <=> u==0). Commit unconditionally: uniform group bookkeeping.
            if (u != 0 && ii + 3 < ICHUNK) {
                const char* src = gbase + (size_t)(ii + 3) * SLB2;
                unsigned dst = ringS + ((ii + 3) & 3) * SLB2;
                for (int k = t; k < SLB_U4; k += THREADS)
                    cp16(dst + k * 16, src + k * 16);
            }
            cp_commit();

            if (u < 3) {
                // ---- crossbar pipe: staged slice, conflict-free LDS.128
                const char* sbuf = dyn + OFF_RING + (ii & 3) * SLB2;
#pragma unroll
                for (int jj = 0; jj < 8; jj++) {
                    unsigned v  = s_gd[ii * BT + wb + 2 * jj + h];
                    unsigned gi = v & 0xFFu;
                    unsigned dd = __byte_perm(v, v, 0x3232);
                    __half2 d2  = *(__half2*)&dd;
                    __half2 w2  = __hsub2(one2, d2);
                    const uint4* pa = (const uint4*)(sbuf + gi * 256) + le;
                    uint4 A  = pa[0];     // row g
                    uint4 Bv = pa[16];    // row g+1 (+256B)
                    hac[jj][0] = __hfma2(d2, *(__half2*)&Bv.x, __hfma2(w2, *(__half2*)&A.x, hac[jj][0]));
                    hac[jj][1] = __hfma2(d2, *(__half2*)&Bv.y, __hfma2(w2, *(__half2*)&A.y, hac[jj][1]));
                    hac[jj][2] = __hfma2(d2, *(__half2*)&Bv.z, __hfma2(w2, *(__half2*)&A.z, hac[jj][2]));
                    hac[jj][3] = __hfma2(d2, *(__half2*)&Bv.w, __hfma2(w2, *(__half2*)&A.w, hac[jj][3]));
                }
            } else {
                // ---- L1 pipe: un-staged slice, uint4 LDG from L2 table
                const uint4* gsl = (const uint4*)(gbase + (size_t)ii * SLB2);
#pragma unroll
                for (int jj = 0; jj < 8; jj++) {
                    unsigned v  = s_gd[ii * BT + wb + 2 * jj + h];
                    unsigned gi = v & 0xFFu;
                    unsigned dd = __byte_perm(v, v, 0x3232);
                    __half2 d2  = *(__half2*)&dd;
                    __half2 w2  = __hsub2(one2, d2);
                    const uint4* pa = gsl + gi * 16 + le;
                    uint4 A  = __ldg(pa);        // row g
                    uint4 Bv = __ldg(pa + 16);   // row g+1
                    hac[jj][0] = __hfma2(d2, *(__half2*)&Bv.x, __hfma2(w2, *(__half2*)&A.x, hac[jj][0]));
                    hac[jj][1] = __hfma2(d2, *(__half2*)&Bv.y, __hfma2(w2, *(__half2*)&A.y, hac[jj][1]));
                    hac[jj][2] = __hfma2(d2, *(__half2*)&Bv.z, __hfma2(w2, *(__half2*)&A.z, hac[jj][2]));
                    hac[jj][3] = __hfma2(d2, *(__half2*)&Bv.w, __hfma2(w2, *(__half2*)&A.w, hac[jj][3]));
                }
            }
        }

        // flush half2 partials into fp32 accumulators every 4 slices
#pragma unroll
        for (int jj = 0; jj < 8; jj++) {
            float2 p0 = __half22float2(hac[jj][0]);
            float2 p1 = __half22float2(hac[jj][1]);
            float2 p2 = __half22float2(hac[jj][2]);
            float2 p3 = __half22float2(hac[jj][3]);
            accF[jj][0].x += p0.x; accF[jj][0].y += p0.y;
            accF[jj][0].z += p1.x; accF[jj][0].w += p1.y;
            accF[jj][1].x += p2.x; accF[jj][1].y += p2.y;
            accF[jj][1].z += p3.x; accF[jj][1].w += p3.y;
        }
    }

    // Store: lane's column = wb + 2jj + h, outputs [8le, 8le+8) -> uint4.
#pragma unroll
    for (int jj = 0; jj < 8; jj++) {
        __half2 q0 = __floats2half2_rn(accF[jj][0].x, accF[jj][0].y);
        __half2 q1 = __floats2half2_rn(accF[jj][0].z, accF[jj][0].w);
        __half2 q2 = __floats2half2_rn(accF[jj][1].x, accF[jj][1].y);
        __half2 q3 = __floats2half2_rn(accF[jj][1].z, accF[jj][1].w);
        uint4 pk;
        pk.x = *(unsigned*)&q0; pk.y = *(unsigned*)&q1;
        pk.z = *(unsigned*)&q2; pk.w = *(unsigned*)&q3;
        int b = b0 + wb + 2 * jj + h;
        *(uint4*)&g_partialH[chunk][b][le * 8] = pk;
    }
}

// ---------------------------------------------------------------------------
// Kernel 3 (stable): sum the 4 fp16 partials, transpose -> out[o][b].
// ---------------------------------------------------------------------------
__global__ void reduce_kernel(float* __restrict__ out) {
    __shared__ float4 tile[32][33];
    const int b0 = blockIdx.x * 32;
    const int tx = threadIdx.x, ty = threadIdx.y;   // (32, 8)
    const size_t cstride = (size_t)B_DIM * (O_DIM / 4);   // in uint2

    const uint2* pbase = (const uint2*)&g_partialH[0][0][0];
#pragma unroll
    for (int r = 0; r < 4; r++) {
        int b = ty + r * 8;
        const uint2* p = pbase + (size_t)(b0 + b) * (O_DIM / 4) + tx;
        float4 s = make_float4(0.f, 0.f, 0.f, 0.f);
#pragma unroll
        for (int c = 0; c < C_CHUNKS; c++) {
            uint2 v = p[c * cstride];
            float2 f0 = __half22float2(*(const __half2*)&v.x);
            float2 f1 = __half22float2(*(const __half2*)&v.y);
            s.x += f0.x; s.y += f0.y; s.z += f1.x; s.w += f1.y;
        }
        tile[b][tx] = s;
    }
    __syncthreads();

    const float* tf = (const float*)tile;   // row stride = 132 floats
#pragma unroll
    for (int r = 0; r < 16; r++) {
        int o = ty + r * 8;
        out[(size_t)o * B_DIM + b0 + tx] = tf[tx * 132 + o];
    }
}

// ---------------------------------------------------------------------------
extern "C" void kernel_launch(void* const* d_in, const int* in_sizes, int n_in,
                              void* d_out, int out_size) {
    const float* x       = (const float*)d_in[0];   // [128, 8192]
    const float* P       = (const float*)d_in[1];   // [129, 128, 128]
    const float* borders = (const float*)d_in[2];   // [129]
    const float* invl    = (const float*)d_in[3];   // [128]
    float*       out     = (float*)d_out;           // [128, 8192]

    cudaFuncSetAttribute(main_kernel,
                         cudaFuncAttributeMaxDynamicSharedMemorySize, SMEM_MAIN);

    transpose_kernel<<<dim3(I_DIM / TI, 65), 256>>>(P);
    main_kernel<<<dim3(NBT, C_CHUNKS), THREADS, SMEM_MAIN>>>(x, borders, invl);
    reduce_kernel<<<B_DIM / 32, dim3(32, 8)>>>(out);
}